// round 4
// baseline (speedup 1.0000x reference)
#include <cuda_runtime.h>
#include <cstdint>

typedef unsigned long long u64;
typedef unsigned int u32;

#define NP 131072
#define NC 128
#define TPB 128
#define NBLK (NP / TPB)   // 1024

__device__ __align__(16) float g_params[NC * 12];
__device__ float g_partial[NBLK];

// ---------------------------------------------------------------------------
// Setup: replicate reference fp32 pipeline for inv_cov (asymmetric rounding!):
//   d = 1/(|r|+1e-8) fp32; R entries fp32 (correctly-rounded trig, fp32 muls);
//   tmp[a][b] = R[a][b]*d[b]; M[a][c] = sum_b tmp[a][b]*R[c][b] (mul+add, seq).
// layout/center: p0={cx,cy,cz,M00} p1={M01,M02,M10,M11} p2={M12,M20,M21,M22}
// ---------------------------------------------------------------------------
__global__ void setup_kernel(const float* __restrict__ centers,
                             const float* __restrict__ radii,
                             const float* __restrict__ rot) {
    int c = threadIdx.x;
    if (c >= NC) return;
    float d[3];
#pragma unroll
    for (int i = 0; i < 3; i++)
        d[i] = __fdiv_rn(1.0f, __fadd_rn(fabsf(radii[c * 3 + i]), 1e-8f));

    float ax = rot[c * 3 + 0], ay = rot[c * 3 + 1], az = rot[c * 3 + 2];
    float cx = (float)cos((double)ax), sx = (float)sin((double)ax);
    float cy = (float)cos((double)ay), sy = (float)sin((double)ay);
    float cz = (float)cos((double)az), sz = (float)sin((double)az);

    float R[3][3];
    R[0][0] = __fmul_rn(cz, cy);
    R[0][1] = __fsub_rn(__fmul_rn(__fmul_rn(cz, sy), sx), __fmul_rn(sz, cx));
    R[0][2] = __fadd_rn(__fmul_rn(__fmul_rn(cz, sy), cx), __fmul_rn(sz, sx));
    R[1][0] = __fmul_rn(sz, cy);
    R[1][1] = __fadd_rn(__fmul_rn(__fmul_rn(sz, sy), sx), __fmul_rn(cz, cx));
    R[1][2] = __fsub_rn(__fmul_rn(__fmul_rn(sz, sy), cx), __fmul_rn(cz, sx));
    R[2][0] = -sy;
    R[2][1] = __fmul_rn(cy, sx);
    R[2][2] = __fmul_rn(cy, cx);

    float tmp[3][3];
#pragma unroll
    for (int a = 0; a < 3; a++)
#pragma unroll
        for (int b = 0; b < 3; b++)
            tmp[a][b] = __fmul_rn(R[a][b], d[b]);

    float M[3][3];
#pragma unroll
    for (int a = 0; a < 3; a++)
#pragma unroll
        for (int cc = 0; cc < 3; cc++)
            M[a][cc] = __fadd_rn(__fadd_rn(__fmul_rn(tmp[a][0], R[cc][0]),
                                           __fmul_rn(tmp[a][1], R[cc][1])),
                                 __fmul_rn(tmp[a][2], R[cc][2]));

    float* o = g_params + c * 12;
    o[0] = centers[c * 3 + 0];
    o[1] = centers[c * 3 + 1];
    o[2] = centers[c * 3 + 2];
    o[3]  = M[0][0];
    o[4]  = M[0][1];
    o[5]  = M[0][2];
    o[6]  = M[1][0];
    o[7]  = M[1][1];
    o[8]  = M[1][2];
    o[9]  = M[2][0];
    o[10] = M[2][1];
    o[11] = M[2][2];
}

// ---------------------------------------------------------------------------
// u64 sorting network (descending; bigger key = better)
// ---------------------------------------------------------------------------
__device__ __forceinline__ void ce_desc(u64& a, u64& b) {
    u64 hi = a > b ? a : b;
    u64 lo = a > b ? b : a;
    a = hi; b = lo;
}

__device__ __forceinline__ void sort16_desc(u64 v[16]) {
#pragma unroll
    for (int p = 1; p < 16; p <<= 1) {
#pragma unroll
        for (int k = p; k >= 1; k >>= 1) {
#pragma unroll
            for (int j = k & (p - 1); j + k < 16; j += 2 * k) {
#pragma unroll
                for (int i = 0; i < k && (i + j + k) < 16; i++) {
                    if (((i + j) / (2 * p)) == ((i + j + k) / (2 * p))) {
                        ce_desc(v[i + j], v[i + j + k]);
                    }
                }
            }
        }
    }
}

__device__ __forceinline__ void merge16_desc(u64 R[16], const u64 C[16]) {
#pragma unroll
    for (int i = 0; i < 16; i++) {
        u64 b = C[15 - i];
        R[i] = R[i] > b ? R[i] : b;
    }
#pragma unroll
    for (int d = 8; d >= 1; d >>= 1) {
#pragma unroll
        for (int i = 0; i < 16; i++) {
            if ((i & d) == 0) ce_desc(R[i], R[i + d]);
        }
    }
}

__device__ __forceinline__ float ex2_fast(float x) {
    float r;
    asm("ex2.approx.f32 %0, %1;" : "=f"(r) : "f"(x));
    return r;
}

// ---------------------------------------------------------------------------
// Main: one thread per point. Rank by q (full fp32 bits), index tiebreak low.
// ---------------------------------------------------------------------------
__global__ void __launch_bounds__(TPB, 3)
main_kernel(const float* __restrict__ xyz,
            const float4* __restrict__ rgbs,
            const float* __restrict__ dists,
            float* __restrict__ out) {
    __shared__ float4 sp[NC * 3];
    __shared__ float sred[TPB];

    int tid = threadIdx.x;
#pragma unroll 3
    for (int i = tid; i < NC * 3; i += TPB)
        sp[i] = reinterpret_cast<const float4*>(g_params)[i];
    __syncthreads();

    int p = blockIdx.x * TPB + tid;
    float x = xyz[3 * p + 0];
    float y = xyz[3 * p + 1];
    float z = xyz[3 * p + 2];

    u64 R[16];
#pragma unroll
    for (int i = 0; i < 16; i++) R[i] = 0ull;

    float pen = 0.0f;
    const float CEXP = -0.72134752044448170f;  // -0.5*log2(e)
    const float K_ADD = 2.3219280948873623f;   // log2(5)

    for (int base = 0; base < NC; base += 16) {
        u64 C[16];
#pragma unroll
        for (int j = 0; j < 16; j++) {
            int c = base + j;
            float4 p0 = sp[c * 3 + 0];
            float4 p1 = sp[c * 3 + 1];
            float4 p2 = sp[c * 3 + 2];
            float dx = x - p0.x, dy = y - p0.y, dz = z - p0.z;
            // t = diff @ M (GEMM fma chain, a = 0,1,2)
            float t0 = fmaf(dz, p2.y, fmaf(dy, p1.z, __fmul_rn(dx, p0.w)));
            float t1 = fmaf(dz, p2.z, fmaf(dy, p1.w, __fmul_rn(dx, p1.x)));
            float t2 = fmaf(dz, p2.w, fmaf(dy, p2.x, __fmul_rn(dx, p1.y)));
            // q = sum_b t_b * diff_b (mul then sequential add)
            float q = __fadd_rn(__fadd_rn(__fmul_rn(t0, dx), __fmul_rn(t1, dy)),
                                __fmul_rn(t2, dz));
            // penalty uses e = 5*exp(-q/2) (approx fine: 1e-9 weight in pen)
            float e = ex2_fast(fmaf(q, CEXP, K_ADD));
            pen += fmaxf(e - 0.01f, 0.0f);
            // key: smaller q better; tie -> lower index (matches lax.top_k)
            u32 qb = __float_as_uint(fmaxf(q, 0.0f));
            C[j] = ((u64)(~qb) << 32) | (u32)(127 - c);
        }
        sort16_desc(C);
        merge16_desc(R, C);
    }

    // decode: w = 5 * 2^(q * -0.5*log2 e), threshold, normalize
    float wv[16];
    u32 idv[16];
    float sumw = 0.0f;
#pragma unroll
    for (int i = 0; i < 16; i++) {
        idv[i] = 127u - (u32)(R[i] & 0x7Fu);
        float q = __uint_as_float(~(u32)(R[i] >> 32));
        float w = __fmul_rn(5.0f, ex2_fast(__fmul_rn(q, CEXP)));
        w = (w >= 0.01f) ? w : 0.0f;
        wv[i] = w;
        sumw += w;
    }

    float inv = __fdiv_rn(1.0f, __fadd_rn(sumw, 1e-7f));
    float dp = dists[p];
    const float LOG2E = 1.4426950408889634f;

    float o0 = 0.0f, o1 = 0.0f, o2 = 0.0f, o3 = 0.0f;
#pragma unroll
    for (int i = 0; i < 16; i++) {
        if (wv[i] > 0.0f) {
            float4 g = __ldg(&rgbs[(size_t)idv[i] * NP + p]);
            float alpha = 1.0f - ex2_fast(fmaxf(g.w, 0.0f) * dp * (-LOG2E));
            float s = wv[i] * inv;
            o0 = fmaf(s, g.x, o0);
            o1 = fmaf(s, g.y, o1);
            o2 = fmaf(s, g.z, o2);
            o3 = fmaf(s, alpha, o3);
        }
    }
    reinterpret_cast<float4*>(out)[p] = make_float4(o0, o1, o2, o3);

    // deterministic block reduction of penalty
    sred[tid] = pen;
    __syncthreads();
#pragma unroll
    for (int s = TPB / 2; s > 0; s >>= 1) {
        if (tid < s) sred[tid] += sred[tid + s];
        __syncthreads();
    }
    if (tid == 0) g_partial[blockIdx.x] = sred[0];
}

// ---------------------------------------------------------------------------
// Finalize: pen = 0.001 * mean + bbox penalty; deterministic order.
// ---------------------------------------------------------------------------
__global__ void finalize_kernel(const float* __restrict__ centers,
                                float* __restrict__ out, int out_size) {
    __shared__ double sd[128];
    int t = threadIdx.x;
    double s = 0.0;
#pragma unroll
    for (int i = 0; i < NBLK / 128; i++)
        s += (double)g_partial[t * (NBLK / 128) + i];
    sd[t] = s;
    __syncthreads();
    if (t == 0) {
        double tot = 0.0;
        for (int i = 0; i < 128; i++) tot += sd[i];
        float bbox = 0.0f;
        for (int i = 0; i < NC * 3; i++) {
            float v = centers[i];
            bbox += fmaxf(v - 0.5f, 0.0f) + fmaxf(-0.5f - v, 0.0f);
        }
        float pen = (float)(0.001 * tot / (double)NP) + bbox;
        if (out_size > 4 * NP) {
            out[4 * NP] = pen;
            out[out_size - 1] = pen;
        }
    }
}

// ---------------------------------------------------------------------------
extern "C" void kernel_launch(void* const* d_in, const int* in_sizes, int n_in,
                              void* d_out, int out_size) {
    const float* xyz = nullptr;
    const float* dists = nullptr;
    const float4* rgbs = nullptr;
    const float* small3[3] = {nullptr, nullptr, nullptr};
    int nsmall = 0;
    for (int i = 0; i < n_in; i++) {
        int sz = in_sizes[i];
        if (sz == NP * 3)                xyz   = (const float*)d_in[i];
        else if (sz == NC * NP * 4)      rgbs  = (const float4*)d_in[i];
        else if (sz == NP)               dists = (const float*)d_in[i];
        else if (sz == NC * 3 && nsmall < 3) small3[nsmall++] = (const float*)d_in[i];
    }
    const float* centers = small3[0];
    const float* radii   = small3[1];
    const float* rots    = small3[2];

    setup_kernel<<<1, 128>>>(centers, radii, rots);
    main_kernel<<<NBLK, TPB>>>(xyz, rgbs, dists, (float*)d_out);
    finalize_kernel<<<1, 128>>>(centers, (float*)d_out, out_size);
}